// round 3
// baseline (speedup 1.0000x reference)
#include <cuda_runtime.h>
#include <cstdint>

#define NN 4
#define PP 128
#define HH 64
#define UU 64
#define BB 15
#define FAVG 49.0f

// ---------------- device scratch ----------------
__device__ float g_rows[NN*HH*PP];     // sum_q x / npart   [n][h][p]
__device__ float g_cols[NN*HH*PP];     // sum_p x / npart   [n][h][q]
__device__ float g_diag[NN*HH*PP];     // x[p,p]            [n][h][p]
__device__ float g_sumdiag[NN*HH];
__device__ float g_sumall[NN*HH];
__device__ float g_C0[HH*UU];
__device__ float g_C1[HH*UU];
__device__ float g_Kq[NN*3*HH*UU];     // terms: 0=diag,1=cols,2=rows
__device__ float g_Kp[NN*3*HH*UU];
__device__ float g_Kd[NN*3*HH*UU];
__device__ float g_Ks[NN*4*HH*UU];     // 0=p_sd,1=p_sa,2=d_sd,3=d_sa
__device__ float g_vp[NN*UU];
__device__ float g_vd[NN*UU];
__device__ float g_Fq[NN*PP*UU];
__device__ float g_Fp[NN*PP*UU];
__device__ float g_Fd[NN*PP*UU];

// ---------------- f32x2 helpers ----------------
#define FMA2(d, a, b) asm("fma.rn.f32x2 %0, %1, %2, %0;" : "+l"(d) : "l"(a), "l"(b))
#define PK2(d, f) do { unsigned int _t = __float_as_uint(f); \
    asm("mov.b64 %0, {%1, %1};" : "=l"(d) : "r"(_t)); } while (0)
#define UPK2(lo, hi, v) asm("mov.b64 {%0, %1}, %2;" : "=f"(lo), "=f"(hi) : "l"(v))

// ---------------- pass 1: row/col/diag reductions ----------------
__global__ void reduce_kernel(const float* __restrict__ x,
                              const float* __restrict__ npart) {
    const int i = blockIdx.x;          // p (z=0) or q (z=1)
    const int n = blockIdx.y;
    const int t = threadIdx.x;
    const int h = t & 63;
    const int c = t >> 6;              // 0..3
    __shared__ float sp[4][64];
    const float inv = 1.0f / npart[n];

    if (blockIdx.z == 0) {
        const float* base = x + ((size_t)(n * PP + i)) * PP * HH;
        float s = 0.0f;
        #pragma unroll 4
        for (int q = c * 32; q < c * 32 + 32; ++q) s += base[q * HH + h];
        sp[c][h] = s;
        __syncthreads();
        if (c == 0) {
            float tot = sp[0][h] + sp[1][h] + sp[2][h] + sp[3][h];
            g_rows[(n * HH + h) * PP + i] = tot * inv;
            g_diag[(n * HH + h) * PP + i] = base[i * HH + h];
        }
    } else {
        const float* base = x + ((size_t)n) * PP * PP * HH + i * HH;
        float s = 0.0f;
        #pragma unroll 4
        for (int p = c * 32; p < c * 32 + 32; ++p) s += base[(size_t)p * PP * HH + h];
        sp[c][h] = s;
        __syncthreads();
        if (c == 0) {
            g_cols[(n * HH + h) * PP + i] =
                (sp[0][h] + sp[1][h] + sp[2][h] + sp[3][h]) * inv;
        }
    }
}

// ---------------- pass 2: per-(n,h) scalars ----------------
__global__ void scalar_kernel(const float* __restrict__ npart) {
    const int n = blockIdx.x;
    const int h = threadIdx.x;
    const float inv = 1.0f / npart[n];
    float sd = 0.0f, sa = 0.0f;
    for (int p = 0; p < PP; ++p) {
        sd += g_diag[(n * HH + h) * PP + p];
        sa += g_rows[(n * HH + h) * PP + p];
    }
    g_sumdiag[n * HH + h] = sd * inv;
    g_sumall[n * HH + h]  = sa * inv;
}

// ---------------- pass 3: folded coefficient matrices (once per n,h) ----------------
__global__ void coef_kernel(const float* __restrict__ npart,
                            const float* __restrict__ alpha0,
                            const float* __restrict__ c00,
                            const float* __restrict__ c01,
                            const float* __restrict__ c10,
                            const float* __restrict__ c11) {
    const int h = blockIdx.x;
    const int n = blockIdx.y;
    const int u = threadIdx.x;
    __shared__ float m[10];
    if (u < 10) m[u] = powf(npart[n] / FAVG, alpha0[h * 10 + u]);
    __syncthreads();
    const float r = c10[h * UU + u] * c11[h * UU + u];
    const float* a = c00 + h * BB;
    if (n == 0) {
        g_C0[h * UU + u] = a[0] * c01[0 * UU + u] * r;
        g_C1[h * UU + u] = a[1] * c01[1 * UU + u] * r;
    }
    const int iq = (n * 3) * HH * UU + h * UU + u;
    const int hu = HH * UU;
    g_Kq[iq + 0*hu] = a[2]  * c01[2  * UU + u] * r;           // d[q]
    g_Kq[iq + 1*hu] = a[5]  * c01[5  * UU + u] * r * m[0];    // cols[q]
    g_Kq[iq + 2*hu] = a[6]  * c01[6  * UU + u] * r * m[1];    // rows[q]
    g_Kp[iq + 0*hu] = a[3]  * c01[3  * UU + u] * r;           // d[p]
    g_Kp[iq + 1*hu] = a[8]  * c01[8  * UU + u] * r * m[3];    // cols[p]
    g_Kp[iq + 2*hu] = a[9]  * c01[9  * UU + u] * r * m[4];    // rows[p]
    g_Kd[iq + 0*hu] = a[4]  * c01[4  * UU + u] * r;           // d[p] on diag
    g_Kd[iq + 1*hu] = a[12] * c01[12 * UU + u] * r * m[7];    // cols[p] on diag
    g_Kd[iq + 2*hu] = a[11] * c01[11 * UU + u] * r * m[6];    // rows[p] on diag
    const int is = (n * 4) * HH * UU + h * UU + u;
    g_Ks[is + 0*hu] = a[7]  * c01[7  * UU + u] * r * m[2];    // p: sum_diag
    g_Ks[is + 1*hu] = a[13] * c01[13 * UU + u] * r * m[8];    // p: sum_all
    g_Ks[is + 2*hu] = a[10] * c01[10 * UU + u] * r * m[5];    // d: sum_diag
    g_Ks[is + 3*hu] = a[14] * c01[14 * UU + u] * r * m[9];    // d: sum_all
}

// ---------------- pass 4: scalar-field vectors ----------------
__global__ void vec_kernel(const float* __restrict__ dbias) {
    const int n = blockIdx.x;
    const int u = threadIdx.x;
    const int hu = HH * UU;
    float vp = 0.0f, vd = 0.0f;
    for (int h = 0; h < HH; ++h) {
        const float sd = g_sumdiag[n * HH + h];
        const float sa = g_sumall[n * HH + h];
        const int is = (n * 4) * hu + h * UU + u;
        vp += g_Ks[is + 0*hu] * sd + g_Ks[is + 1*hu] * sa;
        vd += g_Ks[is + 2*hu] * sd + g_Ks[is + 3*hu] * sa;
    }
    g_vp[n * UU + u] = vp;
    g_vd[n * UU + u] = vd + dbias[u];
}

// ---------------- pass 5: field GEMMs Fq/Fp/Fd ----------------
__global__ void __launch_bounds__(256)
field_kernel(const float* __restrict__ bias) {
    const int n = blockIdx.y;
    const int i0 = blockIdx.x * 16;
    const int tid = threadIdx.x;
    __shared__ float sD[HH][16], sC[HH][16], sR[HH][16];

    {   // cooperative load: 64 rows x 16 cols, float4 per thread per array
        const int hh = tid >> 2;
        const int c4 = (tid & 3) << 2;
        const int gidx = (n * HH + hh) * PP + i0 + c4;
        *(float4*)&sD[hh][c4] = *(const float4*)&g_diag[gidx];
        *(float4*)&sC[hh][c4] = *(const float4*)&g_cols[gidx];
        *(float4*)&sR[hh][c4] = *(const float4*)&g_rows[gidx];
    }
    __syncthreads();

    const int u  = tid & 63;
    const int ib = (tid >> 6) << 2;    // 0,4,8,12
    const int hu = HH * UU;
    float aq[4] = {0,0,0,0}, ap[4] = {0,0,0,0}, ad[4] = {0,0,0,0};

    #pragma unroll 4
    for (int h = 0; h < HH; ++h) {
        const int iq = (n * 3) * hu + h * UU + u;
        const float kqd = g_Kq[iq], kqc = g_Kq[iq + hu], kqr = g_Kq[iq + 2*hu];
        const float kpd = g_Kp[iq], kpc = g_Kp[iq + hu], kpr = g_Kp[iq + 2*hu];
        const float kdd = g_Kd[iq], kdc = g_Kd[iq + hu], kdr = g_Kd[iq + 2*hu];
        const float4 d4 = *(const float4*)&sD[h][ib];
        const float4 c4 = *(const float4*)&sC[h][ib];
        const float4 r4 = *(const float4*)&sR[h][ib];
        const float dv[4] = {d4.x, d4.y, d4.z, d4.w};
        const float cv[4] = {c4.x, c4.y, c4.z, c4.w};
        const float rv[4] = {r4.x, r4.y, r4.z, r4.w};
        #pragma unroll
        for (int j = 0; j < 4; ++j) {
            aq[j] += kqd * dv[j] + kqc * cv[j] + kqr * rv[j];
            ap[j] += kpd * dv[j] + kpc * cv[j] + kpr * rv[j];
            ad[j] += kdd * dv[j] + kdc * cv[j] + kdr * rv[j];
        }
    }

    const float bz = bias[u];
    const float vp = g_vp[n * UU + u];
    const float vd = g_vd[n * UU + u];
    #pragma unroll
    for (int j = 0; j < 4; ++j) {
        const int i = i0 + ib + j;
        g_Fq[(n * PP + i) * UU + u] = aq[j] + bz;
        g_Fp[(n * PP + i) * UU + u] = ap[j] + vp;
        g_Fd[(n * PP + i) * UU + u] = ad[j] + vd;
    }
}

// ---------------- main: dual skinny GEMM with packed f32x2 FMAs ----------------
#define XD_STRIDE 132
constexpr int SMEM_FLOATS = 2 * 64 * XD_STRIDE + 2 * 64 * 64 + 128;

__global__ void __launch_bounds__(256, 2)
main_kernel(const float* __restrict__ x,
            const unsigned int* __restrict__ mask,
            float* __restrict__ out) {
    extern __shared__ float sm[];
    float* sXd = sm;                         // [k=64][q=128+4]
    float* sXt = sXd + 64 * XD_STRIDE;       // [k=64][q=128+4]
    float* sC0 = sXt + 64 * XD_STRIDE;       // [k=64][u=64]
    float* sC1 = sC0 + 64 * 64;
    float* sFp = sC1 + 64 * 64;              // [64]
    float* sFd = sFp + 64;                   // [64]

    const int p = blockIdx.x;
    const int n = blockIdx.y;
    const int tid = threadIdx.x;

    // direct tile: x[n,p,q,h] -> sXd[h][q]
    const float4* xrow4 = (const float4*)(x + ((size_t)(n * PP + p)) * PP * HH);
    #pragma unroll
    for (int it = 0; it < 8; ++it) {
        const int idx4 = tid + it * 256;
        const float4 v = xrow4[idx4];
        const int q  = idx4 >> 4;
        const int h0 = (idx4 & 15) << 2;
        sXd[(h0 + 0) * XD_STRIDE + q] = v.x;
        sXd[(h0 + 1) * XD_STRIDE + q] = v.y;
        sXd[(h0 + 2) * XD_STRIDE + q] = v.z;
        sXd[(h0 + 3) * XD_STRIDE + q] = v.w;
    }
    // transposed tile: x[n,r,p,h] -> sXt[h][r]
    {
        const int h0 = (tid & 15) << 2;
        #pragma unroll
        for (int it = 0; it < 8; ++it) {
            const int r = (tid >> 4) + it * 16;
            const float4 v = *(const float4*)(x + (((size_t)(n * PP + r)) * PP + p) * HH + h0);
            sXt[(h0 + 0) * XD_STRIDE + r] = v.x;
            sXt[(h0 + 1) * XD_STRIDE + r] = v.y;
            sXt[(h0 + 2) * XD_STRIDE + r] = v.z;
            sXt[(h0 + 3) * XD_STRIDE + r] = v.w;
        }
    }
    {
        const float4* c04 = (const float4*)g_C0;
        const float4* c14 = (const float4*)g_C1;
        float4* d0 = (float4*)sC0;
        float4* d1 = (float4*)sC1;
        #pragma unroll
        for (int it = 0; it < 4; ++it) {
            const int i4 = tid + it * 256;
            d0[i4] = c04[i4];
            d1[i4] = c14[i4];
        }
    }
    if (tid < 64) {
        sFp[tid] = g_Fp[(n * PP + p) * UU + tid];
        sFd[tid] = g_Fd[(n * PP + p) * UU + tid];
    }
    __syncthreads();

    const int tx = tid & 15;
    const int ty = tid >> 4;
    const int u0 = tx << 2;
    const int q0 = ty << 3;

    // acc[qpair][u] as packed f32x2: 8 q (4 pairs) x 4 u
    unsigned long long acc[4][4];
    #pragma unroll
    for (int i = 0; i < 4; ++i)
        #pragma unroll
        for (int j = 0; j < 4; ++j) acc[i][j] = 0ULL;

    #pragma unroll 4
    for (int k = 0; k < 64; ++k) {
        const float4 b0 = *(const float4*)(sC0 + k * 64 + u0);
        const float4 b1 = *(const float4*)(sC1 + k * 64 + u0);
        unsigned long long bb0[4], bb1[4];
        PK2(bb0[0], b0.x); PK2(bb0[1], b0.y); PK2(bb0[2], b0.z); PK2(bb0[3], b0.w);
        PK2(bb1[0], b1.x); PK2(bb1[1], b1.y); PK2(bb1[2], b1.z); PK2(bb1[3], b1.w);
        const ulonglong2 a01 = *(const ulonglong2*)(sXd + k * XD_STRIDE + q0);
        const ulonglong2 a23 = *(const ulonglong2*)(sXd + k * XD_STRIDE + q0 + 4);
        const ulonglong2 t01 = *(const ulonglong2*)(sXt + k * XD_STRIDE + q0);
        const ulonglong2 t23 = *(const ulonglong2*)(sXt + k * XD_STRIDE + q0 + 4);
        const unsigned long long av[4] = {a01.x, a01.y, a23.x, a23.y};
        const unsigned long long tv[4] = {t01.x, t01.y, t23.x, t23.y};
        #pragma unroll
        for (int qp = 0; qp < 4; ++qp)
            #pragma unroll
            for (int j = 0; j < 4; ++j) {
                FMA2(acc[qp][j], av[qp], bb0[j]);
                FMA2(acc[qp][j], tv[qp], bb1[j]);
            }
    }

    // epilogue
    const float4 fp4 = *(const float4*)(sFp + u0);
    const float4 fd4 = *(const float4*)(sFd + u0);
    const unsigned int* em = mask + (size_t)(n * PP + p) * PP;
    #pragma unroll
    for (int qp = 0; qp < 4; ++qp) {
        float lo[4], hi[4];
        #pragma unroll
        for (int j = 0; j < 4; ++j) UPK2(lo[j], hi[j], acc[qp][j]);
        #pragma unroll
        for (int half = 0; half < 2; ++half) {
            const int q = q0 + 2 * qp + half;
            const float* v = half ? hi : lo;
            const float4 fq = *(const float4*)(g_Fq + ((size_t)(n * PP + q)) * UU + u0);
            const float msk = (em[q] != 0u) ? 1.0f : 0.0f;
            const float de = (q == p) ? 1.0f : 0.0f;
            float4 o;
            o.x = (v[0] + fq.x + fp4.x + de * fd4.x) * msk;
            o.y = (v[1] + fq.y + fp4.y + de * fd4.y) * msk;
            o.z = (v[2] + fq.z + fp4.z + de * fd4.z) * msk;
            o.w = (v[3] + fq.w + fp4.w + de * fd4.w) * msk;
            *(float4*)(out + (((size_t)(n * PP + p)) * PP + q) * UU + u0) = o;
        }
    }
}

// ---------------- launch ----------------
extern "C" void kernel_launch(void* const* d_in, const int* in_sizes, int n_in,
                              void* d_out, int out_size) {
    (void)in_sizes; (void)n_in; (void)out_size;
    const float*        x      = (const float*)d_in[0];
    const unsigned int* mask   = (const unsigned int*)d_in[1];
    const float*        npart  = (const float*)d_in[2];
    const float*        alpha0 = (const float*)d_in[3];
    const float*        c00    = (const float*)d_in[4];
    const float*        c01    = (const float*)d_in[5];
    const float*        c10    = (const float*)d_in[6];
    const float*        c11    = (const float*)d_in[7];
    const float*        bias   = (const float*)d_in[8];
    const float*        dbias  = (const float*)d_in[9];
    float* out = (float*)d_out;

    reduce_kernel<<<dim3(PP, NN, 2), 256>>>(x, npart);
    coef_kernel<<<dim3(HH, NN), UU>>>(npart, alpha0, c00, c01, c10, c11);
    scalar_kernel<<<NN, HH>>>(npart);
    vec_kernel<<<NN, UU>>>(dbias);
    field_kernel<<<dim3(PP / 16, NN), 256>>>(bias);

    cudaFuncSetAttribute(main_kernel, cudaFuncAttributeMaxDynamicSharedMemorySize,
                         SMEM_FLOATS * 4);
    main_kernel<<<dim3(PP, NN), 256, SMEM_FLOATS * 4>>>(x, mask, out);
}

// round 4
// speedup vs baseline: 1.2233x; 1.2233x over previous
#include <cuda_runtime.h>
#include <cstdint>

#define NN 4
#define PP 128
#define HH 64
#define UU 64
#define BB 15
#define FAVG 49.0f

// ---------------- device scratch ----------------
__device__ float g_rows[NN*HH*PP];     // sum_q x / npart   [n][h][p]
__device__ float g_cols[NN*HH*PP];     // sum_p x / npart   [n][h][q]
__device__ float g_diag[NN*HH*PP];     // x[p,p]            [n][h][p]
__device__ float g_sumdiag[NN*HH];
__device__ float g_sumall[NN*HH];
__device__ float g_C0[HH*UU];
__device__ float g_C1[HH*UU];
__device__ float g_Kq[NN*3*HH*UU];     // terms: 0=diag,1=cols,2=rows
__device__ float g_Kp[NN*3*HH*UU];
__device__ float g_Kd[NN*3*HH*UU];
__device__ float g_vp[NN*UU];
__device__ float g_vd[NN*UU];
__device__ float g_Fq[NN*PP*UU];
__device__ float g_Fp[NN*PP*UU];
__device__ float g_Fd[NN*PP*UU];

// ---------------- f32x2 helpers ----------------
#define FMA2(d, a, b) asm("fma.rn.f32x2 %0, %1, %2, %0;" : "+l"(d) : "l"(a), "l"(b))
#define PK2(d, f) do { unsigned int _t = __float_as_uint(f); \
    asm("mov.b64 %0, {%1, %1};" : "=l"(d) : "r"(_t)); } while (0)
#define UPK2(lo, hi, v) asm("mov.b64 {%0, %1}, %2;" : "=f"(lo), "=f"(hi) : "l"(v))

// ---------------- pass 1: row/col/diag reductions ----------------
__global__ void reduce_kernel(const float* __restrict__ x,
                              const float* __restrict__ npart) {
    const int i = blockIdx.x;          // p (z=0) or q (z=1)
    const int n = blockIdx.y;
    const int t = threadIdx.x;
    const int h = t & 63;
    const int c = t >> 6;              // 0..3
    __shared__ float sp[4][64];
    const float inv = 1.0f / npart[n];

    if (blockIdx.z == 0) {
        const float* base = x + ((size_t)(n * PP + i)) * PP * HH;
        float s = 0.0f;
        #pragma unroll 4
        for (int q = c * 32; q < c * 32 + 32; ++q) s += base[q * HH + h];
        sp[c][h] = s;
        __syncthreads();
        if (c == 0) {
            float tot = sp[0][h] + sp[1][h] + sp[2][h] + sp[3][h];
            g_rows[(n * HH + h) * PP + i] = tot * inv;
            g_diag[(n * HH + h) * PP + i] = base[i * HH + h];
        }
    } else {
        const float* base = x + ((size_t)n) * PP * PP * HH + i * HH;
        float s = 0.0f;
        #pragma unroll 4
        for (int p = c * 32; p < c * 32 + 32; ++p) s += base[(size_t)p * PP * HH + h];
        sp[c][h] = s;
        __syncthreads();
        if (c == 0) {
            g_cols[(n * HH + h) * PP + i] =
                (sp[0][h] + sp[1][h] + sp[2][h] + sp[3][h]) * inv;
        }
    }
}

// ---------------- pass 2: per-(n,h) scalars (parallel, coalesced) ----------------
// Also zeroes g_vp/g_vd for the atomic accumulation in coef_kernel.
__global__ void scalar_kernel(const float* __restrict__ npart) {
    const int b = blockIdx.x;          // n*HH + h
    const int n = b >> 6;
    const int h = b & 63;
    const int p = threadIdx.x;         // 0..127
    __shared__ float swd[4], swa[4];

    const int base = (n * HH + h) * PP;
    float d = g_diag[base + p];
    float r = g_rows[base + p];
    #pragma unroll
    for (int o = 16; o > 0; o >>= 1) {
        d += __shfl_down_sync(0xffffffffu, d, o);
        r += __shfl_down_sync(0xffffffffu, r, o);
    }
    const int lane = p & 31, w = p >> 5;
    if (lane == 0) { swd[w] = d; swa[w] = r; }
    __syncthreads();
    if (p == 0) {
        const float inv = 1.0f / npart[n];
        g_sumdiag[b] = (swd[0] + swd[1] + swd[2] + swd[3]) * inv;
        g_sumall[b]  = (swa[0] + swa[1] + swa[2] + swa[3]) * inv;
        // zero vp/vd once per (n): use h as the u index (HH == UU)
        g_vp[n * UU + h] = 0.0f;
        g_vd[n * UU + h] = 0.0f;
    }
}

// ---------------- pass 3: folded coefficient matrices + scalar-field atomics ----------------
__global__ void coef_kernel(const float* __restrict__ npart,
                            const float* __restrict__ alpha0,
                            const float* __restrict__ c00,
                            const float* __restrict__ c01,
                            const float* __restrict__ c10,
                            const float* __restrict__ c11) {
    const int h = blockIdx.x;
    const int n = blockIdx.y;
    const int u = threadIdx.x;
    __shared__ float m[10];
    if (u < 10) m[u] = powf(npart[n] / FAVG, alpha0[h * 10 + u]);
    __syncthreads();
    const float r = c10[h * UU + u] * c11[h * UU + u];
    const float* a = c00 + h * BB;
    if (n == 0) {
        g_C0[h * UU + u] = a[0] * c01[0 * UU + u] * r;
        g_C1[h * UU + u] = a[1] * c01[1 * UU + u] * r;
    }
    const int iq = (n * 3) * HH * UU + h * UU + u;
    const int hu = HH * UU;
    g_Kq[iq + 0*hu] = a[2]  * c01[2  * UU + u] * r;           // d[q]
    g_Kq[iq + 1*hu] = a[5]  * c01[5  * UU + u] * r * m[0];    // cols[q]
    g_Kq[iq + 2*hu] = a[6]  * c01[6  * UU + u] * r * m[1];    // rows[q]
    g_Kp[iq + 0*hu] = a[3]  * c01[3  * UU + u] * r;           // d[p]
    g_Kp[iq + 1*hu] = a[8]  * c01[8  * UU + u] * r * m[3];    // cols[p]
    g_Kp[iq + 2*hu] = a[9]  * c01[9  * UU + u] * r * m[4];    // rows[p]
    g_Kd[iq + 0*hu] = a[4]  * c01[4  * UU + u] * r;           // d[p] on diag
    g_Kd[iq + 1*hu] = a[12] * c01[12 * UU + u] * r * m[7];    // cols[p] on diag
    g_Kd[iq + 2*hu] = a[11] * c01[11 * UU + u] * r * m[6];    // rows[p] on diag

    // scalar-field contributions (formerly vec_kernel): fold over h via atomics
    const float sd = g_sumdiag[n * HH + h];
    const float sa = g_sumall[n * HH + h];
    const float kp_sd = a[7]  * c01[7  * UU + u] * r * m[2];
    const float kp_sa = a[13] * c01[13 * UU + u] * r * m[8];
    const float kd_sd = a[10] * c01[10 * UU + u] * r * m[5];
    const float kd_sa = a[14] * c01[14 * UU + u] * r * m[9];
    atomicAdd(&g_vp[n * UU + u], kp_sd * sd + kp_sa * sa);
    atomicAdd(&g_vd[n * UU + u], kd_sd * sd + kd_sa * sa);
}

// ---------------- pass 4: field GEMMs Fq/Fp/Fd ----------------
__global__ void __launch_bounds__(256)
field_kernel(const float* __restrict__ bias, const float* __restrict__ dbias) {
    const int n = blockIdx.y;
    const int i0 = blockIdx.x * 16;
    const int tid = threadIdx.x;
    __shared__ float sD[HH][16], sC[HH][16], sR[HH][16];

    {   // cooperative load: 64 rows x 16 cols, float4 per thread per array
        const int hh = tid >> 2;
        const int c4 = (tid & 3) << 2;
        const int gidx = (n * HH + hh) * PP + i0 + c4;
        *(float4*)&sD[hh][c4] = *(const float4*)&g_diag[gidx];
        *(float4*)&sC[hh][c4] = *(const float4*)&g_cols[gidx];
        *(float4*)&sR[hh][c4] = *(const float4*)&g_rows[gidx];
    }
    __syncthreads();

    const int u  = tid & 63;
    const int ib = (tid >> 6) << 2;    // 0,4,8,12
    const int hu = HH * UU;
    float aq[4] = {0,0,0,0}, ap[4] = {0,0,0,0}, ad[4] = {0,0,0,0};

    #pragma unroll 4
    for (int h = 0; h < HH; ++h) {
        const int iq = (n * 3) * hu + h * UU + u;
        const float kqd = g_Kq[iq], kqc = g_Kq[iq + hu], kqr = g_Kq[iq + 2*hu];
        const float kpd = g_Kp[iq], kpc = g_Kp[iq + hu], kpr = g_Kp[iq + 2*hu];
        const float kdd = g_Kd[iq], kdc = g_Kd[iq + hu], kdr = g_Kd[iq + 2*hu];
        const float4 d4 = *(const float4*)&sD[h][ib];
        const float4 c4 = *(const float4*)&sC[h][ib];
        const float4 r4 = *(const float4*)&sR[h][ib];
        const float dv[4] = {d4.x, d4.y, d4.z, d4.w};
        const float cv[4] = {c4.x, c4.y, c4.z, c4.w};
        const float rv[4] = {r4.x, r4.y, r4.z, r4.w};
        #pragma unroll
        for (int j = 0; j < 4; ++j) {
            aq[j] += kqd * dv[j] + kqc * cv[j] + kqr * rv[j];
            ap[j] += kpd * dv[j] + kpc * cv[j] + kpr * rv[j];
            ad[j] += kdd * dv[j] + kdc * cv[j] + kdr * rv[j];
        }
    }

    const float bz = bias[u];
    const float vp = g_vp[n * UU + u];
    const float vd = g_vd[n * UU + u] + dbias[u];
    #pragma unroll
    for (int j = 0; j < 4; ++j) {
        const int i = i0 + ib + j;
        g_Fq[(n * PP + i) * UU + u] = aq[j] + bz;
        g_Fp[(n * PP + i) * UU + u] = ap[j] + vp;
        g_Fd[(n * PP + i) * UU + u] = ad[j] + vd;
    }
}

// ---------------- main: dual skinny GEMM with packed f32x2 FMAs ----------------
#define XD_STRIDE 132
constexpr int SMEM_FLOATS = 2 * 64 * XD_STRIDE + 2 * 64 * 64 + 128;

__global__ void __launch_bounds__(256, 2)
main_kernel(const float* __restrict__ x,
            const unsigned int* __restrict__ mask,
            float* __restrict__ out) {
    extern __shared__ float sm[];
    float* sXd = sm;                         // [k=64][q=128+4]
    float* sXt = sXd + 64 * XD_STRIDE;       // [k=64][q=128+4]
    float* sC0 = sXt + 64 * XD_STRIDE;       // [k=64][u=64]
    float* sC1 = sC0 + 64 * 64;
    float* sFp = sC1 + 64 * 64;              // [64]
    float* sFd = sFp + 64;                   // [64]

    const int p = blockIdx.x;
    const int n = blockIdx.y;
    const int tid = threadIdx.x;

    // direct tile: x[n,p,q,h] -> sXd[h][q]
    const float4* xrow4 = (const float4*)(x + ((size_t)(n * PP + p)) * PP * HH);
    #pragma unroll
    for (int it = 0; it < 8; ++it) {
        const int idx4 = tid + it * 256;
        const float4 v = xrow4[idx4];
        const int q  = idx4 >> 4;
        const int h0 = (idx4 & 15) << 2;
        sXd[(h0 + 0) * XD_STRIDE + q] = v.x;
        sXd[(h0 + 1) * XD_STRIDE + q] = v.y;
        sXd[(h0 + 2) * XD_STRIDE + q] = v.z;
        sXd[(h0 + 3) * XD_STRIDE + q] = v.w;
    }
    // transposed tile: x[n,r,p,h] -> sXt[h][r]
    {
        const int h0 = (tid & 15) << 2;
        #pragma unroll
        for (int it = 0; it < 8; ++it) {
            const int r = (tid >> 4) + it * 16;
            const float4 v = *(const float4*)(x + (((size_t)(n * PP + r)) * PP + p) * HH + h0);
            sXt[(h0 + 0) * XD_STRIDE + r] = v.x;
            sXt[(h0 + 1) * XD_STRIDE + r] = v.y;
            sXt[(h0 + 2) * XD_STRIDE + r] = v.z;
            sXt[(h0 + 3) * XD_STRIDE + r] = v.w;
        }
    }
    {
        const float4* c04 = (const float4*)g_C0;
        const float4* c14 = (const float4*)g_C1;
        float4* d0 = (float4*)sC0;
        float4* d1 = (float4*)sC1;
        #pragma unroll
        for (int it = 0; it < 4; ++it) {
            const int i4 = tid + it * 256;
            d0[i4] = c04[i4];
            d1[i4] = c14[i4];
        }
    }
    if (tid < 64) {
        sFp[tid] = g_Fp[(n * PP + p) * UU + tid];
        sFd[tid] = g_Fd[(n * PP + p) * UU + tid];
    }
    __syncthreads();

    const int tx = tid & 15;
    const int ty = tid >> 4;
    const int u0 = tx << 2;
    const int q0 = ty << 3;

    // acc[qpair][u] as packed f32x2: 8 q (4 pairs) x 4 u
    unsigned long long acc[4][4];
    #pragma unroll
    for (int i = 0; i < 4; ++i)
        #pragma unroll
        for (int j = 0; j < 4; ++j) acc[i][j] = 0ULL;

    #pragma unroll 4
    for (int k = 0; k < 64; ++k) {
        const float4 b0 = *(const float4*)(sC0 + k * 64 + u0);
        const float4 b1 = *(const float4*)(sC1 + k * 64 + u0);
        unsigned long long bb0[4], bb1[4];
        PK2(bb0[0], b0.x); PK2(bb0[1], b0.y); PK2(bb0[2], b0.z); PK2(bb0[3], b0.w);
        PK2(bb1[0], b1.x); PK2(bb1[1], b1.y); PK2(bb1[2], b1.z); PK2(bb1[3], b1.w);
        const ulonglong2 a01 = *(const ulonglong2*)(sXd + k * XD_STRIDE + q0);
        const ulonglong2 a23 = *(const ulonglong2*)(sXd + k * XD_STRIDE + q0 + 4);
        const ulonglong2 t01 = *(const ulonglong2*)(sXt + k * XD_STRIDE + q0);
        const ulonglong2 t23 = *(const ulonglong2*)(sXt + k * XD_STRIDE + q0 + 4);
        const unsigned long long av[4] = {a01.x, a01.y, a23.x, a23.y};
        const unsigned long long tv[4] = {t01.x, t01.y, t23.x, t23.y};
        #pragma unroll
        for (int qp = 0; qp < 4; ++qp)
            #pragma unroll
            for (int j = 0; j < 4; ++j) {
                FMA2(acc[qp][j], av[qp], bb0[j]);
                FMA2(acc[qp][j], tv[qp], bb1[j]);
            }
    }

    // epilogue
    const float4 fp4 = *(const float4*)(sFp + u0);
    const float4 fd4 = *(const float4*)(sFd + u0);
    const unsigned int* em = mask + (size_t)(n * PP + p) * PP;
    #pragma unroll
    for (int qp = 0; qp < 4; ++qp) {
        float lo[4], hi[4];
        #pragma unroll
        for (int j = 0; j < 4; ++j) UPK2(lo[j], hi[j], acc[qp][j]);
        #pragma unroll
        for (int half = 0; half < 2; ++half) {
            const int q = q0 + 2 * qp + half;
            const float* v = half ? hi : lo;
            const float4 fq = *(const float4*)(g_Fq + ((size_t)(n * PP + q)) * UU + u0);
            const float msk = (em[q] != 0u) ? 1.0f : 0.0f;
            const float de = (q == p) ? 1.0f : 0.0f;
            float4 o;
            o.x = (v[0] + fq.x + fp4.x + de * fd4.x) * msk;
            o.y = (v[1] + fq.y + fp4.y + de * fd4.y) * msk;
            o.z = (v[2] + fq.z + fp4.z + de * fd4.z) * msk;
            o.w = (v[3] + fq.w + fp4.w + de * fd4.w) * msk;
            *(float4*)(out + (((size_t)(n * PP + p)) * PP + q) * UU + u0) = o;
        }
    }
}

// ---------------- launch ----------------
extern "C" void kernel_launch(void* const* d_in, const int* in_sizes, int n_in,
                              void* d_out, int out_size) {
    (void)in_sizes; (void)n_in; (void)out_size;
    const float*        x      = (const float*)d_in[0];
    const unsigned int* mask   = (const unsigned int*)d_in[1];
    const float*        npart  = (const float*)d_in[2];
    const float*        alpha0 = (const float*)d_in[3];
    const float*        c00    = (const float*)d_in[4];
    const float*        c01    = (const float*)d_in[5];
    const float*        c10    = (const float*)d_in[6];
    const float*        c11    = (const float*)d_in[7];
    const float*        bias   = (const float*)d_in[8];
    const float*        dbias  = (const float*)d_in[9];
    float* out = (float*)d_out;

    reduce_kernel<<<dim3(PP, NN, 2), 256>>>(x, npart);
    scalar_kernel<<<NN * HH, PP>>>(npart);
    coef_kernel<<<dim3(HH, NN), UU>>>(npart, alpha0, c00, c01, c10, c11);
    field_kernel<<<dim3(PP / 16, NN), 256>>>(bias, dbias);

    cudaFuncSetAttribute(main_kernel, cudaFuncAttributeMaxDynamicSharedMemorySize,
                         SMEM_FLOATS * 4);
    main_kernel<<<dim3(PP, NN), 256, SMEM_FLOATS * 4>>>(x, mask, out);
}

// round 5
// speedup vs baseline: 1.8311x; 1.4969x over previous
#include <cuda_runtime.h>
#include <cstdint>

#define NN 4
#define PP 128
#define HH 64
#define UU 64
#define BB 15
#define FAVG 49.0f

// ---------------- device scratch ----------------
__device__ float g_rows[NN*HH*PP];     // sum_q x / npart   [n][h][p]
__device__ float g_cols[NN*HH*PP];     // sum_p x / npart   [n][h][q]
__device__ float g_diag[NN*HH*PP];     // x[p,p]            [n][h][p]
__device__ float g_Fq[NN*PP*UU];       // q-field (includes bias)
__device__ float g_Fp[NN*PP*UU];       // p-field (includes scalar terms)
__device__ float g_Fd[NN*PP*UU];       // diag field (includes diag_bias + scalar terms)

// ---------------- f32x2 helpers ----------------
#define FMA2(d, a, b) asm("fma.rn.f32x2 %0, %1, %2, %0;" : "+l"(d) : "l"(a), "l"(b))
#define PK2(d, f) do { unsigned int _t = __float_as_uint(f); \
    asm("mov.b64 %0, {%1, %1};" : "=l"(d) : "r"(_t)); } while (0)
#define UPK2(lo, hi, v) asm("mov.b64 {%0, %1}, %2;" : "=f"(lo), "=f"(hi) : "l"(v))

// ---------------- pass 1: row/col/diag reductions ----------------
__global__ void reduce_kernel(const float* __restrict__ x,
                              const float* __restrict__ npart) {
    const int i = blockIdx.x;          // p (z=0) or q (z=1)
    const int n = blockIdx.y;
    const int t = threadIdx.x;
    const int h = t & 63;
    const int c = t >> 6;              // 0..3
    __shared__ float sp[4][64];
    const float inv = 1.0f / npart[n];

    if (blockIdx.z == 0) {
        const float* base = x + ((size_t)(n * PP + i)) * PP * HH;
        float s = 0.0f;
        #pragma unroll 4
        for (int q = c * 32; q < c * 32 + 32; ++q) s += base[q * HH + h];
        sp[c][h] = s;
        __syncthreads();
        if (c == 0) {
            float tot = sp[0][h] + sp[1][h] + sp[2][h] + sp[3][h];
            g_rows[(n * HH + h) * PP + i] = tot * inv;
            g_diag[(n * HH + h) * PP + i] = base[i * HH + h];
        }
    } else {
        const float* base = x + ((size_t)n) * PP * PP * HH + i * HH;
        float s = 0.0f;
        #pragma unroll 4
        for (int p = c * 32; p < c * 32 + 32; ++p) s += base[(size_t)p * PP * HH + h];
        sp[c][h] = s;
        __syncthreads();
        if (c == 0) {
            g_cols[(n * HH + h) * PP + i] =
                (sp[0][h] + sp[1][h] + sp[2][h] + sp[3][h]) * inv;
        }
    }
}

// ---------------- pass 2 (fused): scalars + coefficients + field GEMMs ----------------
// grid (16, NN), block 256. Block handles 8 i-values for one n.
// Recomputes the tiny K-coefficient algebra per block (cheap) to avoid a
// produce->consume chain of separate kernels.
__global__ void __launch_bounds__(256)
pro_kernel(const float* __restrict__ npart,
           const float* __restrict__ alpha0,
           const float* __restrict__ c00,
           const float* __restrict__ c01,
           const float* __restrict__ c10,
           const float* __restrict__ c11,
           const float* __restrict__ bias,
           const float* __restrict__ dbias) {
    const int n  = blockIdx.y;
    const int i0 = blockIdx.x * 8;
    const int tid = threadIdx.x;

    __shared__ float sD[HH][8], sC[HH][8], sR[HH][8];
    __shared__ float sSD[HH], sSA[HH];
    __shared__ float sM[HH][10];
    __shared__ float sA[HH][16];       // c00 rows (15 used)

    const float np  = npart[n];
    const float inv = 1.0f / np;

    // slice loads: d/c/r at i0..i0+7 for all h
    {
        const int hh = tid >> 2;
        const int ii = (tid & 3) << 1;
        const int gi = (n * HH + hh) * PP + i0 + ii;
        *(float2*)&sD[hh][ii] = *(const float2*)&g_diag[gi];
        *(float2*)&sC[hh][ii] = *(const float2*)&g_cols[gi];
        *(float2*)&sR[hh][ii] = *(const float2*)&g_rows[gi];
    }
    // sd/sa: warp w reduces h = w*8..w*8+7
    {
        const int w = tid >> 5, lane = tid & 31;
        #pragma unroll
        for (int j = 0; j < 8; ++j) {
            const int h = w * 8 + j;
            const int base = (n * HH + h) * PP;
            float d = g_diag[base + lane] + g_diag[base + lane + 32]
                    + g_diag[base + lane + 64] + g_diag[base + lane + 96];
            float r = g_rows[base + lane] + g_rows[base + lane + 32]
                    + g_rows[base + lane + 64] + g_rows[base + lane + 96];
            #pragma unroll
            for (int o = 16; o > 0; o >>= 1) {
                d += __shfl_down_sync(0xffffffffu, d, o);
                r += __shfl_down_sync(0xffffffffu, r, o);
            }
            if (lane == 0) { sSD[h] = d * inv; sSA[h] = r * inv; }
        }
    }
    // powf multipliers
    {
        const float ratio = np / FAVG;
        for (int idx = tid; idx < HH * 10; idx += 256)
            sM[idx / 10][idx % 10] = powf(ratio, alpha0[idx]);
    }
    // stage c00
    for (int idx = tid; idx < HH * BB; idx += 256)
        sA[idx / BB][idx % BB] = c00[idx];
    __syncthreads();

    const int u  = tid & 63;
    const int ig = (tid >> 6) << 1;    // 0,2,4,6 -> thread covers i offsets ig, ig+1

    // hoist c01 columns
    float cb[BB];
    #pragma unroll
    for (int b = 2; b < BB; ++b) cb[b] = c01[b * UU + u];

    float aq[2] = {0, 0}, ap[2] = {0, 0}, ad[2] = {0, 0};
    float vp = 0.0f, vd = 0.0f;

    #pragma unroll 2
    for (int h = 0; h < HH; ++h) {
        const float r = c10[h * UU + u] * c11[h * UU + u];
        const float* a = sA[h];
        const float* m = sM[h];
        const float kqd = a[2]  * cb[2]  * r;
        const float kqc = a[5]  * cb[5]  * r * m[0];
        const float kqr = a[6]  * cb[6]  * r * m[1];
        const float kpd = a[3]  * cb[3]  * r;
        const float kpc = a[8]  * cb[8]  * r * m[3];
        const float kpr = a[9]  * cb[9]  * r * m[4];
        const float kdd = a[4]  * cb[4]  * r;
        const float kdc = a[12] * cb[12] * r * m[7];
        const float kdr = a[11] * cb[11] * r * m[6];
        vp += (a[7]  * cb[7]  * r * m[2]) * sSD[h] + (a[13] * cb[13] * r * m[8]) * sSA[h];
        vd += (a[10] * cb[10] * r * m[5]) * sSD[h] + (a[14] * cb[14] * r * m[9]) * sSA[h];
        #pragma unroll
        for (int j = 0; j < 2; ++j) {
            const float d  = sD[h][ig + j];
            const float cl = sC[h][ig + j];
            const float rw = sR[h][ig + j];
            aq[j] += kqd * d + kqc * cl + kqr * rw;
            ap[j] += kpd * d + kpc * cl + kpr * rw;
            ad[j] += kdd * d + kdc * cl + kdr * rw;
        }
    }

    const float bz = bias[u];
    const float db = dbias[u];
    #pragma unroll
    for (int j = 0; j < 2; ++j) {
        const int i = i0 + ig + j;
        g_Fq[(n * PP + i) * UU + u] = aq[j] + bz;
        g_Fp[(n * PP + i) * UU + u] = ap[j] + vp;
        g_Fd[(n * PP + i) * UU + u] = ad[j] + vd + db;
    }
}

// ---------------- main: dual skinny GEMM with packed f32x2 FMAs ----------------
#define XD_STRIDE 132
constexpr int SMEM_FLOATS = 2 * 64 * XD_STRIDE + 2 * 64 * 64 + 128;

__global__ void __launch_bounds__(256, 2)
main_kernel(const float* __restrict__ x,
            const unsigned int* __restrict__ mask,
            const float* __restrict__ c00,
            const float* __restrict__ c01,
            const float* __restrict__ c10,
            const float* __restrict__ c11,
            float* __restrict__ out) {
    extern __shared__ float sm[];
    float* sXd = sm;                         // [k=64][q=128+4]
    float* sXt = sXd + 64 * XD_STRIDE;       // [k=64][q=128+4]
    float* sC0 = sXt + 64 * XD_STRIDE;       // [k=64][u=64]
    float* sC1 = sC0 + 64 * 64;
    float* sFp = sC1 + 64 * 64;              // [64]
    float* sFd = sFp + 64;                   // [64]

    const int p = blockIdx.x;
    const int n = blockIdx.y;
    const int tid = threadIdx.x;

    // direct tile: x[n,p,q,h] -> sXd[h][q]
    const float4* xrow4 = (const float4*)(x + ((size_t)(n * PP + p)) * PP * HH);
    #pragma unroll
    for (int it = 0; it < 8; ++it) {
        const int idx4 = tid + it * 256;
        const float4 v = xrow4[idx4];
        const int q  = idx4 >> 4;
        const int h0 = (idx4 & 15) << 2;
        sXd[(h0 + 0) * XD_STRIDE + q] = v.x;
        sXd[(h0 + 1) * XD_STRIDE + q] = v.y;
        sXd[(h0 + 2) * XD_STRIDE + q] = v.z;
        sXd[(h0 + 3) * XD_STRIDE + q] = v.w;
    }
    // transposed tile: x[n,r,p,h] -> sXt[h][r]
    {
        const int h0 = (tid & 15) << 2;
        #pragma unroll
        for (int it = 0; it < 8; ++it) {
            const int r = (tid >> 4) + it * 16;
            const float4 v = *(const float4*)(x + (((size_t)(n * PP + r)) * PP + p) * HH + h0);
            sXt[(h0 + 0) * XD_STRIDE + r] = v.x;
            sXt[(h0 + 1) * XD_STRIDE + r] = v.y;
            sXt[(h0 + 2) * XD_STRIDE + r] = v.z;
            sXt[(h0 + 3) * XD_STRIDE + r] = v.w;
        }
    }
    // compute C0/C1 in-block from raw coefficients (removes coef kernel dep)
    #pragma unroll
    for (int it = 0; it < 16; ++it) {
        const int idx = tid + it * 256;      // 0..4095 = h*64+u
        const int h = idx >> 6;
        const int uu = idx & 63;
        const float r = c10[idx] * c11[idx];
        sC0[idx] = c00[h * BB + 0] * c01[uu] * r;
        sC1[idx] = c00[h * BB + 1] * c01[UU + uu] * r;
    }
    if (tid < 64) {
        sFp[tid] = g_Fp[(n * PP + p) * UU + tid];
        sFd[tid] = g_Fd[(n * PP + p) * UU + tid];
    }
    __syncthreads();

    const int tx = tid & 15;
    const int ty = tid >> 4;
    const int u0 = tx << 2;
    const int q0 = ty << 3;

    // acc[qpair][u] as packed f32x2: 8 q (4 pairs) x 4 u
    unsigned long long acc[4][4];
    #pragma unroll
    for (int i = 0; i < 4; ++i)
        #pragma unroll
        for (int j = 0; j < 4; ++j) acc[i][j] = 0ULL;

    #pragma unroll 4
    for (int k = 0; k < 64; ++k) {
        const float4 b0 = *(const float4*)(sC0 + k * 64 + u0);
        const float4 b1 = *(const float4*)(sC1 + k * 64 + u0);
        unsigned long long bb0[4], bb1[4];
        PK2(bb0[0], b0.x); PK2(bb0[1], b0.y); PK2(bb0[2], b0.z); PK2(bb0[3], b0.w);
        PK2(bb1[0], b1.x); PK2(bb1[1], b1.y); PK2(bb1[2], b1.z); PK2(bb1[3], b1.w);
        const ulonglong2 a01 = *(const ulonglong2*)(sXd + k * XD_STRIDE + q0);
        const ulonglong2 a23 = *(const ulonglong2*)(sXd + k * XD_STRIDE + q0 + 4);
        const ulonglong2 t01 = *(const ulonglong2*)(sXt + k * XD_STRIDE + q0);
        const ulonglong2 t23 = *(const ulonglong2*)(sXt + k * XD_STRIDE + q0 + 4);
        const unsigned long long av[4] = {a01.x, a01.y, a23.x, a23.y};
        const unsigned long long tv[4] = {t01.x, t01.y, t23.x, t23.y};
        #pragma unroll
        for (int qp = 0; qp < 4; ++qp)
            #pragma unroll
            for (int j = 0; j < 4; ++j) {
                FMA2(acc[qp][j], av[qp], bb0[j]);
                FMA2(acc[qp][j], tv[qp], bb1[j]);
            }
    }

    // epilogue
    const float4 fp4 = *(const float4*)(sFp + u0);
    const float4 fd4 = *(const float4*)(sFd + u0);
    const unsigned int* em = mask + (size_t)(n * PP + p) * PP;
    #pragma unroll
    for (int qp = 0; qp < 4; ++qp) {
        float lo[4], hi[4];
        #pragma unroll
        for (int j = 0; j < 4; ++j) UPK2(lo[j], hi[j], acc[qp][j]);
        #pragma unroll
        for (int half = 0; half < 2; ++half) {
            const int q = q0 + 2 * qp + half;
            const float* v = half ? hi : lo;
            const float4 fq = *(const float4*)(g_Fq + ((size_t)(n * PP + q)) * UU + u0);
            const float msk = (em[q] != 0u) ? 1.0f : 0.0f;
            const float de = (q == p) ? 1.0f : 0.0f;
            float4 o;
            o.x = (v[0] + fq.x + fp4.x + de * fd4.x) * msk;
            o.y = (v[1] + fq.y + fp4.y + de * fd4.y) * msk;
            o.z = (v[2] + fq.z + fp4.z + de * fd4.z) * msk;
            o.w = (v[3] + fq.w + fp4.w + de * fd4.w) * msk;
            *(float4*)(out + (((size_t)(n * PP + p)) * PP + q) * UU + u0) = o;
        }
    }
}

// ---------------- launch ----------------
extern "C" void kernel_launch(void* const* d_in, const int* in_sizes, int n_in,
                              void* d_out, int out_size) {
    (void)in_sizes; (void)n_in; (void)out_size;
    const float*        x      = (const float*)d_in[0];
    const unsigned int* mask   = (const unsigned int*)d_in[1];
    const float*        npart  = (const float*)d_in[2];
    const float*        alpha0 = (const float*)d_in[3];
    const float*        c00    = (const float*)d_in[4];
    const float*        c01    = (const float*)d_in[5];
    const float*        c10    = (const float*)d_in[6];
    const float*        c11    = (const float*)d_in[7];
    const float*        bias   = (const float*)d_in[8];
    const float*        dbias  = (const float*)d_in[9];
    float* out = (float*)d_out;

    reduce_kernel<<<dim3(PP, NN, 2), 256>>>(x, npart);
    pro_kernel<<<dim3(16, NN), 256>>>(npart, alpha0, c00, c01, c10, c11, bias, dbias);

    cudaFuncSetAttribute(main_kernel, cudaFuncAttributeMaxDynamicSharedMemorySize,
                         SMEM_FLOATS * 4);
    main_kernel<<<dim3(PP, NN), 256, SMEM_FLOATS * 4>>>(x, mask, c00, c01, c10, c11, out);
}

// round 6
// speedup vs baseline: 2.1001x; 1.1469x over previous
#include <cuda_runtime.h>
#include <cstdint>

#define NN 4
#define PP 128
#define HH 64
#define UU 64
#define BB 15
#define FAVG 49.0f

// ---------------- device scratch ----------------
__device__ float g_rows[NN*HH*PP];     // sum_q x / npart   [n][h][p]
__device__ float g_cols[NN*HH*PP];     // sum_p x / npart   [n][h][q]
__device__ float g_diag[NN*HH*PP];     // x[p,p]            [n][h][p]
__device__ float g_Fq[NN*PP*UU];       // q-field (includes bias)
__device__ float g_Fp[NN*PP*UU];       // p-field (includes scalar terms)
__device__ float g_Fd[NN*PP*UU];       // diag field (includes diag_bias + scalar terms)

// ---------------- f32x2 helpers ----------------
#define FMA2(d, a, b) asm("fma.rn.f32x2 %0, %1, %2, %0;" : "+l"(d) : "l"(a), "l"(b))
#define PK2(d, f) do { unsigned int _t = __float_as_uint(f); \
    asm("mov.b64 %0, {%1, %1};" : "=l"(d) : "r"(_t)); } while (0)
#define UPK2(lo, hi, v) asm("mov.b64 {%0, %1}, %2;" : "=f"(lo), "=f"(hi) : "l"(v))

// ---------------- pass 1: row/col/diag reductions ----------------
__global__ void reduce_kernel(const float* __restrict__ x,
                              const float* __restrict__ npart) {
    const int i = blockIdx.x;          // p (z=0) or q (z=1)
    const int n = blockIdx.y;
    const int t = threadIdx.x;
    const int h = t & 63;
    const int c = t >> 6;              // 0..3
    __shared__ float sp[4][64];
    const float inv = 1.0f / npart[n];

    if (blockIdx.z == 0) {
        const float* base = x + ((size_t)(n * PP + i)) * PP * HH;
        float s = 0.0f;
        #pragma unroll 4
        for (int q = c * 32; q < c * 32 + 32; ++q) s += base[q * HH + h];
        sp[c][h] = s;
        __syncthreads();
        if (c == 0) {
            float tot = sp[0][h] + sp[1][h] + sp[2][h] + sp[3][h];
            g_rows[(n * HH + h) * PP + i] = tot * inv;
            g_diag[(n * HH + h) * PP + i] = base[i * HH + h];
        }
    } else {
        const float* base = x + ((size_t)n) * PP * PP * HH + i * HH;
        float s = 0.0f;
        #pragma unroll 4
        for (int p = c * 32; p < c * 32 + 32; ++p) s += base[(size_t)p * PP * HH + h];
        sp[c][h] = s;
        __syncthreads();
        if (c == 0) {
            g_cols[(n * HH + h) * PP + i] =
                (sp[0][h] + sp[1][h] + sp[2][h] + sp[3][h]) * inv;
        }
    }
}

// ---------------- pass 2 (fused): scalars + coefficients + field GEMMs ----------------
// grid (32, NN), block 256. Block handles 4 i-values for one n; 1 i per thread.
// All coefficient data staged in smem -> zero global loads inside the h-loop.
__global__ void __launch_bounds__(256)
pro_kernel(const float* __restrict__ npart,
           const float* __restrict__ alpha0,
           const float* __restrict__ c00,
           const float* __restrict__ c01,
           const float* __restrict__ c10,
           const float* __restrict__ c11,
           const float* __restrict__ bias,
           const float* __restrict__ dbias) {
    const int n  = blockIdx.y;
    const int i0 = blockIdx.x * 4;
    const int tid = threadIdx.x;

    __shared__ float sRR[HH * UU];     // c10*c11  [h][u]   16KB
    __shared__ float sD[HH][4], sC[HH][4], sR[HH][4];
    __shared__ float sSD[HH], sSA[HH];
    __shared__ float sM[HH][10];
    __shared__ float sA[HH][16];       // c00 rows (15 used)

    const float np  = npart[n];
    const float inv = 1.0f / np;

    // stage c10*c11 (coalesced)
    #pragma unroll
    for (int it = 0; it < 16; ++it) {
        const int idx = tid + it * 256;
        sRR[idx] = c10[idx] * c11[idx];
    }
    // slice loads: d/c/r at i0..i0+3 for all h
    {
        const int hh = tid >> 2;
        const int ii = tid & 3;
        const int gi = (n * HH + hh) * PP + i0 + ii;
        sD[hh][ii] = g_diag[gi];
        sC[hh][ii] = g_cols[gi];
        sR[hh][ii] = g_rows[gi];
    }
    // sd/sa: warp w reduces h = w*8..w*8+7
    {
        const int w = tid >> 5, lane = tid & 31;
        #pragma unroll
        for (int j = 0; j < 8; ++j) {
            const int h = w * 8 + j;
            const int base = (n * HH + h) * PP;
            float d = g_diag[base + lane] + g_diag[base + lane + 32]
                    + g_diag[base + lane + 64] + g_diag[base + lane + 96];
            float r = g_rows[base + lane] + g_rows[base + lane + 32]
                    + g_rows[base + lane + 64] + g_rows[base + lane + 96];
            #pragma unroll
            for (int o = 16; o > 0; o >>= 1) {
                d += __shfl_down_sync(0xffffffffu, d, o);
                r += __shfl_down_sync(0xffffffffu, r, o);
            }
            if (lane == 0) { sSD[h] = d * inv; sSA[h] = r * inv; }
        }
    }
    // powf multipliers
    {
        const float ratio = np / FAVG;
        for (int idx = tid; idx < HH * 10; idx += 256)
            sM[idx / 10][idx % 10] = powf(ratio, alpha0[idx]);
    }
    // stage c00
    for (int idx = tid; idx < HH * BB; idx += 256)
        sA[idx / BB][idx % BB] = c00[idx];
    __syncthreads();

    const int u  = tid & 63;
    const int ii = tid >> 6;           // 0..3: this thread's i offset

    // hoist c01 columns
    float cb[BB];
    #pragma unroll
    for (int b = 2; b < BB; ++b) cb[b] = c01[b * UU + u];

    float aq = 0.0f, ap = 0.0f, ad = 0.0f, vp = 0.0f, vd = 0.0f;

    #pragma unroll 4
    for (int h = 0; h < HH; ++h) {
        const float r = sRR[h * UU + u];
        const float* a = sA[h];
        const float* m = sM[h];
        const float d  = sD[h][ii];
        const float cl = sC[h][ii];
        const float rw = sR[h][ii];
        aq += (a[2]  * cb[2]  * r)        * d
            + (a[5]  * cb[5]  * r * m[0]) * cl
            + (a[6]  * cb[6]  * r * m[1]) * rw;
        ap += (a[3]  * cb[3]  * r)        * d
            + (a[8]  * cb[8]  * r * m[3]) * cl
            + (a[9]  * cb[9]  * r * m[4]) * rw;
        ad += (a[4]  * cb[4]  * r)        * d
            + (a[12] * cb[12] * r * m[7]) * cl
            + (a[11] * cb[11] * r * m[6]) * rw;
        vp += (a[7]  * cb[7]  * r * m[2]) * sSD[h]
            + (a[13] * cb[13] * r * m[8]) * sSA[h];
        vd += (a[10] * cb[10] * r * m[5]) * sSD[h]
            + (a[14] * cb[14] * r * m[9]) * sSA[h];
    }

    const int i = i0 + ii;
    g_Fq[(n * PP + i) * UU + u] = aq + bias[u];
    g_Fp[(n * PP + i) * UU + u] = ap + vp;
    g_Fd[(n * PP + i) * UU + u] = ad + vd + dbias[u];
}

// ---------------- main: dual skinny GEMM with packed f32x2 FMAs ----------------
#define XD_STRIDE 132
constexpr int SMEM_FLOATS = 2 * 64 * XD_STRIDE + 2 * 64 * 64 + 128;

__global__ void __launch_bounds__(256, 2)
main_kernel(const float* __restrict__ x,
            const unsigned int* __restrict__ mask,
            const float* __restrict__ c00,
            const float* __restrict__ c01,
            const float* __restrict__ c10,
            const float* __restrict__ c11,
            float* __restrict__ out) {
    extern __shared__ float sm[];
    float* sXd = sm;                         // [k=64][q=128+4]
    float* sXt = sXd + 64 * XD_STRIDE;       // [k=64][q=128+4]
    float* sC0 = sXt + 64 * XD_STRIDE;       // [k=64][u=64]
    float* sC1 = sC0 + 64 * 64;
    float* sFp = sC1 + 64 * 64;              // [64]
    float* sFd = sFp + 64;                   // [64]

    const int p = blockIdx.x;
    const int n = blockIdx.y;
    const int tid = threadIdx.x;

    // direct tile: x[n,p,q,h] -> sXd[h][q]
    const float4* xrow4 = (const float4*)(x + ((size_t)(n * PP + p)) * PP * HH);
    #pragma unroll
    for (int it = 0; it < 8; ++it) {
        const int idx4 = tid + it * 256;
        const float4 v = xrow4[idx4];
        const int q  = idx4 >> 4;
        const int h0 = (idx4 & 15) << 2;
        sXd[(h0 + 0) * XD_STRIDE + q] = v.x;
        sXd[(h0 + 1) * XD_STRIDE + q] = v.y;
        sXd[(h0 + 2) * XD_STRIDE + q] = v.z;
        sXd[(h0 + 3) * XD_STRIDE + q] = v.w;
    }
    // transposed tile: x[n,r,p,h] -> sXt[h][r]
    {
        const int h0 = (tid & 15) << 2;
        #pragma unroll
        for (int it = 0; it < 8; ++it) {
            const int r = (tid >> 4) + it * 16;
            const float4 v = *(const float4*)(x + (((size_t)(n * PP + r)) * PP + p) * HH + h0);
            sXt[(h0 + 0) * XD_STRIDE + r] = v.x;
            sXt[(h0 + 1) * XD_STRIDE + r] = v.y;
            sXt[(h0 + 2) * XD_STRIDE + r] = v.z;
            sXt[(h0 + 3) * XD_STRIDE + r] = v.w;
        }
    }
    // compute C0/C1 in-block from raw coefficients
    #pragma unroll
    for (int it = 0; it < 16; ++it) {
        const int idx = tid + it * 256;      // 0..4095 = h*64+u
        const int h = idx >> 6;
        const int uu = idx & 63;
        const float r = c10[idx] * c11[idx];
        sC0[idx] = c00[h * BB + 0] * c01[uu] * r;
        sC1[idx] = c00[h * BB + 1] * c01[UU + uu] * r;
    }
    if (tid < 64) {
        sFp[tid] = g_Fp[(n * PP + p) * UU + tid];
        sFd[tid] = g_Fd[(n * PP + p) * UU + tid];
    }
    __syncthreads();

    const int tx = tid & 15;
    const int ty = tid >> 4;
    const int u0 = tx << 2;
    const int q0 = ty << 3;

    // acc[qpair][u] as packed f32x2: 8 q (4 pairs) x 4 u
    unsigned long long acc[4][4];
    #pragma unroll
    for (int i = 0; i < 4; ++i)
        #pragma unroll
        for (int j = 0; j < 4; ++j) acc[i][j] = 0ULL;

    #pragma unroll 4
    for (int k = 0; k < 64; ++k) {
        const float4 b0 = *(const float4*)(sC0 + k * 64 + u0);
        const float4 b1 = *(const float4*)(sC1 + k * 64 + u0);
        unsigned long long bb0[4], bb1[4];
        PK2(bb0[0], b0.x); PK2(bb0[1], b0.y); PK2(bb0[2], b0.z); PK2(bb0[3], b0.w);
        PK2(bb1[0], b1.x); PK2(bb1[1], b1.y); PK2(bb1[2], b1.z); PK2(bb1[3], b1.w);
        const ulonglong2 a01 = *(const ulonglong2*)(sXd + k * XD_STRIDE + q0);
        const ulonglong2 a23 = *(const ulonglong2*)(sXd + k * XD_STRIDE + q0 + 4);
        const ulonglong2 t01 = *(const ulonglong2*)(sXt + k * XD_STRIDE + q0);
        const ulonglong2 t23 = *(const ulonglong2*)(sXt + k * XD_STRIDE + q0 + 4);
        const unsigned long long av[4] = {a01.x, a01.y, a23.x, a23.y};
        const unsigned long long tv[4] = {t01.x, t01.y, t23.x, t23.y};
        #pragma unroll
        for (int qp = 0; qp < 4; ++qp)
            #pragma unroll
            for (int j = 0; j < 4; ++j) {
                FMA2(acc[qp][j], av[qp], bb0[j]);
                FMA2(acc[qp][j], tv[qp], bb1[j]);
            }
    }

    // epilogue
    const float4 fp4 = *(const float4*)(sFp + u0);
    const float4 fd4 = *(const float4*)(sFd + u0);
    const unsigned int* em = mask + (size_t)(n * PP + p) * PP;
    #pragma unroll
    for (int qp = 0; qp < 4; ++qp) {
        float lo[4], hi[4];
        #pragma unroll
        for (int j = 0; j < 4; ++j) UPK2(lo[j], hi[j], acc[qp][j]);
        #pragma unroll
        for (int half = 0; half < 2; ++half) {
            const int q = q0 + 2 * qp + half;
            const float* v = half ? hi : lo;
            const float4 fq = *(const float4*)(g_Fq + ((size_t)(n * PP + q)) * UU + u0);
            const float msk = (em[q] != 0u) ? 1.0f : 0.0f;
            const float de = (q == p) ? 1.0f : 0.0f;
            float4 o;
            o.x = (v[0] + fq.x + fp4.x + de * fd4.x) * msk;
            o.y = (v[1] + fq.y + fp4.y + de * fd4.y) * msk;
            o.z = (v[2] + fq.z + fp4.z + de * fd4.z) * msk;
            o.w = (v[3] + fq.w + fp4.w + de * fd4.w) * msk;
            *(float4*)(out + (((size_t)(n * PP + p)) * PP + q) * UU + u0) = o;
        }
    }
}

// ---------------- launch ----------------
extern "C" void kernel_launch(void* const* d_in, const int* in_sizes, int n_in,
                              void* d_out, int out_size) {
    (void)in_sizes; (void)n_in; (void)out_size;
    const float*        x      = (const float*)d_in[0];
    const unsigned int* mask   = (const unsigned int*)d_in[1];
    const float*        npart  = (const float*)d_in[2];
    const float*        alpha0 = (const float*)d_in[3];
    const float*        c00    = (const float*)d_in[4];
    const float*        c01    = (const float*)d_in[5];
    const float*        c10    = (const float*)d_in[6];
    const float*        c11    = (const float*)d_in[7];
    const float*        bias   = (const float*)d_in[8];
    const float*        dbias  = (const float*)d_in[9];
    float* out = (float*)d_out;

    reduce_kernel<<<dim3(PP, NN, 2), 256>>>(x, npart);
    pro_kernel<<<dim3(32, NN), 256>>>(npart, alpha0, c00, c01, c10, c11, bias, dbias);

    cudaFuncSetAttribute(main_kernel, cudaFuncAttributeMaxDynamicSharedMemorySize,
                         SMEM_FLOATS * 4);
    main_kernel<<<dim3(PP, NN), 256, SMEM_FLOATS * 4>>>(x, mask, c00, c01, c10, c11, out);
}

// round 7
// speedup vs baseline: 2.1829x; 1.0394x over previous
#include <cuda_runtime.h>
#include <cstdint>

#define NN 4
#define PP 128
#define HH 64
#define UU 64
#define BB 15
#define FAVG 49.0f

// ---------------- device scratch ----------------
__device__ float g_rows[NN*HH*PP];     // sum_q x / npart   [n][h][p]
__device__ float g_cols[NN*HH*PP];     // sum_p x / npart   [n][h][q]
__device__ float g_diag[NN*HH*PP];     // x[p,p]            [n][h][p]
__device__ float g_Fq[NN*PP*UU];       // q-field (includes bias)
__device__ float g_Fp[NN*PP*UU];       // p-field (includes scalar terms)
__device__ float g_Fd[NN*PP*UU];       // diag field (includes diag_bias + scalar terms)

// ---------------- f32x2 helpers ----------------
#define FMA2(d, a, b) asm("fma.rn.f32x2 %0, %1, %2, %0;" : "+l"(d) : "l"(a), "l"(b))
#define PK2(d, f) do { unsigned int _t = __float_as_uint(f); \
    asm("mov.b64 %0, {%1, %1};" : "=l"(d) : "r"(_t)); } while (0)
#define UPK2(lo, hi, v) asm("mov.b64 {%0, %1}, %2;" : "=f"(lo), "=f"(hi) : "l"(v))

// XOR swizzle on 8-float q-chunks, keyed by h>>2 (bits 3..5 of q)
#define SWZ(h, q) ((q) ^ ((((h) >> 2) & 7) << 3))

// ---------------- pass 1: row/col/diag reductions (float4, MLP=8) ----------------
__global__ void reduce_kernel(const float* __restrict__ x,
                              const float* __restrict__ npart) {
    const int i = blockIdx.x;          // p (z=0) or q (z=1)
    const int n = blockIdx.y;
    const int t = threadIdx.x;         // 256
    const int h4 = t & 15;             // float4 h-group (h = 4*h4..4*h4+3)
    const int c  = t >> 4;             // 0..15, chunk of 8 along reduce dim
    __shared__ float4 sp[16][17];
    const float inv = 1.0f / npart[n];

    float4 s = make_float4(0.f, 0.f, 0.f, 0.f);
    const float4* xb;
    if (blockIdx.z == 0) {
        // rowsum over q for fixed p=i (contiguous 32KB slab)
        xb = (const float4*)x + (size_t)(n * PP + i) * (PP * HH / 4);
        #pragma unroll
        for (int j = 0; j < 8; ++j) {
            const float4 v = xb[(c * 8 + j) * 16 + h4];
            s.x += v.x; s.y += v.y; s.z += v.z; s.w += v.w;
        }
    } else {
        // colsum over p for fixed q=i (stride 32KB, 8 outstanding)
        xb = (const float4*)x + (size_t)n * (PP * PP * HH / 4) + i * 16;
        #pragma unroll
        for (int j = 0; j < 8; ++j) {
            const float4 v = xb[(size_t)(c * 8 + j) * (PP * HH / 4) + h4];
            s.x += v.x; s.y += v.y; s.z += v.z; s.w += v.w;
        }
    }
    sp[c][h4] = s;
    __syncthreads();

    if (t < 16) {
        float4 tot = sp[0][t];
        #pragma unroll
        for (int cc = 1; cc < 16; ++cc) {
            const float4 v = sp[cc][t];
            tot.x += v.x; tot.y += v.y; tot.z += v.z; tot.w += v.w;
        }
        const int h0 = t * 4;
        const int gb = (n * HH + h0) * PP + i;
        if (blockIdx.z == 0) {
            g_rows[gb + 0*PP] = tot.x * inv;
            g_rows[gb + 1*PP] = tot.y * inv;
            g_rows[gb + 2*PP] = tot.z * inv;
            g_rows[gb + 3*PP] = tot.w * inv;
            const float4 d = xb[i * 16 + t];     // diagonal element x[p=i, q=i, h]
            g_diag[gb + 0*PP] = d.x;
            g_diag[gb + 1*PP] = d.y;
            g_diag[gb + 2*PP] = d.z;
            g_diag[gb + 3*PP] = d.w;
        } else {
            g_cols[gb + 0*PP] = tot.x * inv;
            g_cols[gb + 1*PP] = tot.y * inv;
            g_cols[gb + 2*PP] = tot.z * inv;
            g_cols[gb + 3*PP] = tot.w * inv;
        }
    }
}

// ---------------- pass 2 (fused): scalars + coefficients + field GEMMs ----------------
__global__ void __launch_bounds__(256)
pro_kernel(const float* __restrict__ npart,
           const float* __restrict__ alpha0,
           const float* __restrict__ c00,
           const float* __restrict__ c01,
           const float* __restrict__ c10,
           const float* __restrict__ c11,
           const float* __restrict__ bias,
           const float* __restrict__ dbias) {
    const int n  = blockIdx.y;
    const int i0 = blockIdx.x * 4;
    const int tid = threadIdx.x;

    __shared__ float sRR[HH * UU];     // c10*c11  [h][u]
    __shared__ float sD[HH][4], sC[HH][4], sR[HH][4];
    __shared__ float sSD[HH], sSA[HH];
    __shared__ float sM[HH][10];
    __shared__ float sA[HH][16];       // c00 rows (15 used)

    const float np  = npart[n];
    const float inv = 1.0f / np;

    #pragma unroll
    for (int it = 0; it < 16; ++it) {
        const int idx = tid + it * 256;
        sRR[idx] = c10[idx] * c11[idx];
    }
    {
        const int hh = tid >> 2;
        const int ii = tid & 3;
        const int gi = (n * HH + hh) * PP + i0 + ii;
        sD[hh][ii] = g_diag[gi];
        sC[hh][ii] = g_cols[gi];
        sR[hh][ii] = g_rows[gi];
    }
    {
        const int w = tid >> 5, lane = tid & 31;
        #pragma unroll
        for (int j = 0; j < 8; ++j) {
            const int h = w * 8 + j;
            const int base = (n * HH + h) * PP;
            float d = g_diag[base + lane] + g_diag[base + lane + 32]
                    + g_diag[base + lane + 64] + g_diag[base + lane + 96];
            float r = g_rows[base + lane] + g_rows[base + lane + 32]
                    + g_rows[base + lane + 64] + g_rows[base + lane + 96];
            #pragma unroll
            for (int o = 16; o > 0; o >>= 1) {
                d += __shfl_down_sync(0xffffffffu, d, o);
                r += __shfl_down_sync(0xffffffffu, r, o);
            }
            if (lane == 0) { sSD[h] = d * inv; sSA[h] = r * inv; }
        }
    }
    {
        const float ratio = np / FAVG;
        for (int idx = tid; idx < HH * 10; idx += 256)
            sM[idx / 10][idx % 10] = powf(ratio, alpha0[idx]);
    }
    for (int idx = tid; idx < HH * BB; idx += 256)
        sA[idx / BB][idx % BB] = c00[idx];
    __syncthreads();

    const int u  = tid & 63;
    const int ii = tid >> 6;

    float cb[BB];
    #pragma unroll
    for (int b = 2; b < BB; ++b) cb[b] = c01[b * UU + u];

    float aq = 0.0f, ap = 0.0f, ad = 0.0f, vp = 0.0f, vd = 0.0f;

    #pragma unroll 4
    for (int h = 0; h < HH; ++h) {
        const float r = sRR[h * UU + u];
        const float* a = sA[h];
        const float* m = sM[h];
        const float d  = sD[h][ii];
        const float cl = sC[h][ii];
        const float rw = sR[h][ii];
        aq += (a[2]  * cb[2]  * r)        * d
            + (a[5]  * cb[5]  * r * m[0]) * cl
            + (a[6]  * cb[6]  * r * m[1]) * rw;
        ap += (a[3]  * cb[3]  * r)        * d
            + (a[8]  * cb[8]  * r * m[3]) * cl
            + (a[9]  * cb[9]  * r * m[4]) * rw;
        ad += (a[4]  * cb[4]  * r)        * d
            + (a[12] * cb[12] * r * m[7]) * cl
            + (a[11] * cb[11] * r * m[6]) * rw;
        vp += (a[7]  * cb[7]  * r * m[2]) * sSD[h]
            + (a[13] * cb[13] * r * m[8]) * sSA[h];
        vd += (a[10] * cb[10] * r * m[5]) * sSD[h]
            + (a[14] * cb[14] * r * m[9]) * sSA[h];
    }

    const int i = i0 + ii;
    g_Fq[(n * PP + i) * UU + u] = aq + bias[u];
    g_Fp[(n * PP + i) * UU + u] = ap + vp;
    g_Fd[(n * PP + i) * UU + u] = ad + vd + dbias[u];
}

// ---------------- main: dual skinny GEMM with packed f32x2 FMAs ----------------
constexpr int SMEM_FLOATS = 2 * 64 * 128 + 2 * 64 * 64 + 128;

__global__ void __launch_bounds__(256, 2)
main_kernel(const float* __restrict__ x,
            const unsigned int* __restrict__ mask,
            const float* __restrict__ c00,
            const float* __restrict__ c01,
            const float* __restrict__ c10,
            const float* __restrict__ c11,
            float* __restrict__ out) {
    extern __shared__ float sm[];
    float* sXd = sm;                         // [k=64][q=128] XOR-swizzled
    float* sXt = sXd + 64 * 128;             // [k=64][q=128] XOR-swizzled
    float* sC0 = sXt + 64 * 128;             // [k=64][u=64]
    float* sC1 = sC0 + 64 * 64;
    float* sFp = sC1 + 64 * 64;              // [64]
    float* sFd = sFp + 64;                   // [64]

    const int p = blockIdx.x;
    const int n = blockIdx.y;
    const int tid = threadIdx.x;

    // direct tile: x[n,p,q,h] -> sXd[h][swz(q)]
    const float4* xrow4 = (const float4*)(x + ((size_t)(n * PP + p)) * PP * HH);
    #pragma unroll
    for (int it = 0; it < 8; ++it) {
        const int idx4 = tid + it * 256;           // [q][h/4]
        const float4 v = xrow4[idx4];
        const int q  = idx4 >> 4;
        const int h0 = (idx4 & 15) << 2;
        const int qs = q ^ ((idx4 & 7) << 3);      // swizzle key = h>>2 = idx4&15 (low3 = idx4&7)
        sXd[(h0 + 0) * 128 + qs] = v.x;
        sXd[(h0 + 1) * 128 + qs] = v.y;
        sXd[(h0 + 2) * 128 + qs] = v.z;
        sXd[(h0 + 3) * 128 + qs] = v.w;
    }
    // transposed tile: x[n,r,p,h] -> sXt[h][swz(r)]
    {
        const int h0 = (tid & 15) << 2;
        const int sw = (tid & 7) << 3;             // key = h>>2 = tid&15 (low3)
        #pragma unroll
        for (int it = 0; it < 8; ++it) {
            const int r = (tid >> 4) + it * 16;
            const float4 v = *(const float4*)(x + (((size_t)(n * PP + r)) * PP + p) * HH + h0);
            const int rs = r ^ sw;
            sXt[(h0 + 0) * 128 + rs] = v.x;
            sXt[(h0 + 1) * 128 + rs] = v.y;
            sXt[(h0 + 2) * 128 + rs] = v.z;
            sXt[(h0 + 3) * 128 + rs] = v.w;
        }
    }
    // compute C0/C1 in-block from raw coefficients
    #pragma unroll
    for (int it = 0; it < 16; ++it) {
        const int idx = tid + it * 256;      // 0..4095 = h*64+u
        const int h = idx >> 6;
        const int uu = idx & 63;
        const float r = c10[idx] * c11[idx];
        sC0[idx] = c00[h * BB + 0] * c01[uu] * r;
        sC1[idx] = c00[h * BB + 1] * c01[UU + uu] * r;
    }
    if (tid < 64) {
        sFp[tid] = g_Fp[(n * PP + p) * UU + tid];
        sFd[tid] = g_Fd[(n * PP + p) * UU + tid];
    }
    __syncthreads();

    const int tx = tid & 15;
    const int ty = tid >> 4;
    const int u0 = tx << 2;
    const int q0 = ty << 3;

    unsigned long long acc[4][4];
    #pragma unroll
    for (int i = 0; i < 4; ++i)
        #pragma unroll
        for (int j = 0; j < 4; ++j) acc[i][j] = 0ULL;

    #pragma unroll 4
    for (int k = 0; k < 64; ++k) {
        const float4 b0 = *(const float4*)(sC0 + k * 64 + u0);
        const float4 b1 = *(const float4*)(sC1 + k * 64 + u0);
        unsigned long long bb0[4], bb1[4];
        PK2(bb0[0], b0.x); PK2(bb0[1], b0.y); PK2(bb0[2], b0.z); PK2(bb0[3], b0.w);
        PK2(bb1[0], b1.x); PK2(bb1[1], b1.y); PK2(bb1[2], b1.z); PK2(bb1[3], b1.w);
        const int kq = k * 128 + (q0 ^ (((k >> 2) & 7) << 3));
        const ulonglong2 a01 = *(const ulonglong2*)(sXd + kq);
        const ulonglong2 a23 = *(const ulonglong2*)(sXd + kq + 4);
        const ulonglong2 t01 = *(const ulonglong2*)(sXt + kq);
        const ulonglong2 t23 = *(const ulonglong2*)(sXt + kq + 4);
        const unsigned long long av[4] = {a01.x, a01.y, a23.x, a23.y};
        const unsigned long long tv[4] = {t01.x, t01.y, t23.x, t23.y};
        #pragma unroll
        for (int qp = 0; qp < 4; ++qp)
            #pragma unroll
            for (int j = 0; j < 4; ++j) {
                FMA2(acc[qp][j], av[qp], bb0[j]);
                FMA2(acc[qp][j], tv[qp], bb1[j]);
            }
    }

    // epilogue
    const float4 fp4 = *(const float4*)(sFp + u0);
    const float4 fd4 = *(const float4*)(sFd + u0);
    const unsigned int* em = mask + (size_t)(n * PP + p) * PP;
    #pragma unroll
    for (int qp = 0; qp < 4; ++qp) {
        float lo[4], hi[4];
        #pragma unroll
        for (int j = 0; j < 4; ++j) UPK2(lo[j], hi[j], acc[qp][j]);
        #pragma unroll
        for (int half = 0; half < 2; ++half) {
            const int q = q0 + 2 * qp + half;
            const float* v = half ? hi : lo;
            const float4 fq = *(const float4*)(g_Fq + ((size_t)(n * PP + q)) * UU + u0);
            const float msk = (em[q] != 0u) ? 1.0f : 0.0f;
            const float de = (q == p) ? 1.0f : 0.0f;
            float4 o;
            o.x = (v[0] + fq.x + fp4.x + de * fd4.x) * msk;
            o.y = (v[1] + fq.y + fp4.y + de * fd4.y) * msk;
            o.z = (v[2] + fq.z + fp4.z + de * fd4.z) * msk;
            o.w = (v[3] + fq.w + fp4.w + de * fd4.w) * msk;
            *(float4*)(out + (((size_t)(n * PP + p)) * PP + q) * UU + u0) = o;
        }
    }
}

// ---------------- launch ----------------
extern "C" void kernel_launch(void* const* d_in, const int* in_sizes, int n_in,
                              void* d_out, int out_size) {
    (void)in_sizes; (void)n_in; (void)out_size;
    const float*        x      = (const float*)d_in[0];
    const unsigned int* mask   = (const unsigned int*)d_in[1];
    const float*        npart  = (const float*)d_in[2];
    const float*        alpha0 = (const float*)d_in[3];
    const float*        c00    = (const float*)d_in[4];
    const float*        c01    = (const float*)d_in[5];
    const float*        c10    = (const float*)d_in[6];
    const float*        c11    = (const float*)d_in[7];
    const float*        bias   = (const float*)d_in[8];
    const float*        dbias  = (const float*)d_in[9];
    float* out = (float*)d_out;

    reduce_kernel<<<dim3(PP, NN, 2), 256>>>(x, npart);
    pro_kernel<<<dim3(32, NN), 256>>>(npart, alpha0, c00, c01, c10, c11, bias, dbias);

    cudaFuncSetAttribute(main_kernel, cudaFuncAttributeMaxDynamicSharedMemorySize,
                         SMEM_FLOATS * 4);
    main_kernel<<<dim3(PP, NN), 256, SMEM_FLOATS * 4>>>(x, mask, c00, c01, c10, c11, out);
}

// round 8
// speedup vs baseline: 2.1937x; 1.0050x over previous
#include <cuda_runtime.h>
#include <cstdint>

#define NN 4
#define PP 128
#define HH 64
#define UU 64
#define BB 15
#define FAVG 49.0f

// ---------------- device scratch ----------------
__device__ float g_rows[NN*HH*PP];        // sum_q x / npart   [n][h][p]
__device__ float g_diag[NN*HH*PP];        // x[p,p]            [n][h][p]
__device__ float g_cpart[32*NN*PP*HH];    // partial colsums   [pg][n][q][h]  (4MB)
__device__ float g_Fq[NN*PP*UU];          // q-field (includes bias)
__device__ float g_Fp[NN*PP*UU];          // p-field (includes scalar terms)
__device__ float g_Fd[NN*PP*UU];          // diag field (includes diag_bias + scalar terms)

// ---------------- f32x2 helpers ----------------
#define FMA2(d, a, b) asm("fma.rn.f32x2 %0, %1, %2, %0;" : "+l"(d) : "l"(a), "l"(b))
#define PK2(d, f) do { unsigned int _t = __float_as_uint(f); \
    asm("mov.b64 %0, {%1, %1};" : "=l"(d) : "r"(_t)); } while (0)
#define UPK2(lo, hi, v) asm("mov.b64 {%0, %1}, %2;" : "=f"(lo), "=f"(hi) : "l"(v))

// ---------------- pass 1 (fused): single x read -> rows, diag, colsum partials ----------------
// grid (32, NN), 256 threads. Block covers p in [p0, p0+4).
__global__ void __launch_bounds__(256)
fuse_kernel(const float* __restrict__ x, const float* __restrict__ npart) {
    const int pg = blockIdx.x;         // p-group (4 p's)
    const int n  = blockIdx.y;
    const int p0 = pg * 4;
    const int t  = threadIdx.x;
    const int h4 = t & 15;             // float4 h-group
    const int qg = t >> 4;             // 0..15

    __shared__ float4 spart[16][4][16];   // [qg][p][h4] rowsum partials (16KB)

    const float4* x4 = (const float4*)x;
    const float inv = 1.0f / npart[n];

    float4 col[8];
    #pragma unroll
    for (int j = 0; j < 8; ++j) col[j] = make_float4(0.f, 0.f, 0.f, 0.f);

    #pragma unroll
    for (int p = 0; p < 4; ++p) {
        float4 rp = make_float4(0.f, 0.f, 0.f, 0.f);
        const size_t base = ((size_t)(n * PP + p0 + p)) * PP * 16;  // float4 units
        #pragma unroll
        for (int j = 0; j < 8; ++j) {
            const int q = qg + j * 16;
            const float4 v = x4[base + q * 16 + h4];
            col[j].x += v.x; col[j].y += v.y; col[j].z += v.z; col[j].w += v.w;
            rp.x += v.x; rp.y += v.y; rp.z += v.z; rp.w += v.w;
        }
        spart[qg][p][h4] = rp;
    }

    // colsum partials -> g_cpart[pg][n][q][h] (plain float4 stores)
    {
        float4* cp = (float4*)g_cpart + ((size_t)(pg * NN + n)) * PP * 16;
        #pragma unroll
        for (int j = 0; j < 8; ++j)
            cp[(qg + j * 16) * 16 + h4] = col[j];
    }
    __syncthreads();

    // rowsum finish + diag: threads 0..63 -> (p = t>>4, h4 = t&15)
    if (t < 64) {
        const int p  = t >> 4;
        const int hh4 = t & 15;
        float4 r = spart[0][p][hh4];
        #pragma unroll
        for (int g = 1; g < 16; ++g) {
            const float4 v = spart[g][p][hh4];
            r.x += v.x; r.y += v.y; r.z += v.z; r.w += v.w;
        }
        const int P = p0 + p;
        const int gb = (n * HH + hh4 * 4) * PP + P;
        g_rows[gb + 0*PP] = r.x * inv;
        g_rows[gb + 1*PP] = r.y * inv;
        g_rows[gb + 2*PP] = r.z * inv;
        g_rows[gb + 3*PP] = r.w * inv;
        const float4 d = x4[(((size_t)(n * PP + P)) * PP + P) * 16 + hh4];
        g_diag[gb + 0*PP] = d.x;
        g_diag[gb + 1*PP] = d.y;
        g_diag[gb + 2*PP] = d.z;
        g_diag[gb + 3*PP] = d.w;
    }
}

// ---------------- pass 2 (fused): scalars + coefficients + field GEMMs ----------------
__global__ void __launch_bounds__(256)
pro_kernel(const float* __restrict__ npart,
           const float* __restrict__ alpha0,
           const float* __restrict__ c00,
           const float* __restrict__ c01,
           const float* __restrict__ c10,
           const float* __restrict__ c11,
           const float* __restrict__ bias,
           const float* __restrict__ dbias) {
    const int n  = blockIdx.y;
    const int i0 = blockIdx.x * 4;
    const int tid = threadIdx.x;

    __shared__ float sRR[HH * UU];     // c10*c11  [h][u]
    __shared__ float sD[HH][4], sC[HH][4], sR[HH][4];
    __shared__ float sSD[HH], sSA[HH];
    __shared__ float sM[HH][10];
    __shared__ float sA[HH][16];       // c00 rows (15 used)

    const float np  = npart[n];
    const float inv = 1.0f / np;

    #pragma unroll
    for (int it = 0; it < 16; ++it) {
        const int idx = tid + it * 256;
        sRR[idx] = c10[idx] * c11[idx];
    }
    // sD/sR slices
    {
        const int hh = tid >> 2;
        const int ii = tid & 3;
        const int gi = (n * HH + hh) * PP + i0 + ii;
        sD[hh][ii] = g_diag[gi];
        sR[hh][ii] = g_rows[gi];
    }
    // colsum: fold 32 partials; thread (hh = tid&63, ii = tid>>6), coalesced over hh
    {
        const int hh = tid & 63;
        const int ii = tid >> 6;
        const float* cp = g_cpart + ((size_t)n * PP + i0 + ii) * HH + hh;
        float s = 0.0f;
        #pragma unroll 8
        for (int g = 0; g < 32; ++g)
            s += cp[(size_t)g * (NN * PP * HH)];
        sC[hh][ii] = s * inv;
    }
    // sd/sa: warp w reduces h = w*8..w*8+7
    {
        const int w = tid >> 5, lane = tid & 31;
        #pragma unroll
        for (int j = 0; j < 8; ++j) {
            const int h = w * 8 + j;
            const int base = (n * HH + h) * PP;
            float d = g_diag[base + lane] + g_diag[base + lane + 32]
                    + g_diag[base + lane + 64] + g_diag[base + lane + 96];
            float r = g_rows[base + lane] + g_rows[base + lane + 32]
                    + g_rows[base + lane + 64] + g_rows[base + lane + 96];
            #pragma unroll
            for (int o = 16; o > 0; o >>= 1) {
                d += __shfl_down_sync(0xffffffffu, d, o);
                r += __shfl_down_sync(0xffffffffu, r, o);
            }
            if (lane == 0) { sSD[h] = d * inv; sSA[h] = r * inv; }
        }
    }
    {
        const float ratio = np / FAVG;
        for (int idx = tid; idx < HH * 10; idx += 256)
            sM[idx / 10][idx % 10] = powf(ratio, alpha0[idx]);
    }
    for (int idx = tid; idx < HH * BB; idx += 256)
        sA[idx / BB][idx % BB] = c00[idx];
    __syncthreads();

    const int u  = tid & 63;
    const int ii = tid >> 6;

    float cb[BB];
    #pragma unroll
    for (int b = 2; b < BB; ++b) cb[b] = c01[b * UU + u];

    float aq = 0.0f, ap = 0.0f, ad = 0.0f, vp = 0.0f, vd = 0.0f;

    #pragma unroll 4
    for (int h = 0; h < HH; ++h) {
        const float r = sRR[h * UU + u];
        const float* a = sA[h];
        const float* m = sM[h];
        const float d  = sD[h][ii];
        const float cl = sC[h][ii];
        const float rw = sR[h][ii];
        aq += (a[2]  * cb[2]  * r)        * d
            + (a[5]  * cb[5]  * r * m[0]) * cl
            + (a[6]  * cb[6]  * r * m[1]) * rw;
        ap += (a[3]  * cb[3]  * r)        * d
            + (a[8]  * cb[8]  * r * m[3]) * cl
            + (a[9]  * cb[9]  * r * m[4]) * rw;
        ad += (a[4]  * cb[4]  * r)        * d
            + (a[12] * cb[12] * r * m[7]) * cl
            + (a[11] * cb[11] * r * m[6]) * rw;
        vp += (a[7]  * cb[7]  * r * m[2]) * sSD[h]
            + (a[13] * cb[13] * r * m[8]) * sSA[h];
        vd += (a[10] * cb[10] * r * m[5]) * sSD[h]
            + (a[14] * cb[14] * r * m[9]) * sSA[h];
    }

    const int i = i0 + ii;
    g_Fq[(n * PP + i) * UU + u] = aq + bias[u];
    g_Fp[(n * PP + i) * UU + u] = ap + vp;
    g_Fd[(n * PP + i) * UU + u] = ad + vd + dbias[u];
}

// ---------------- main: dual skinny GEMM with packed f32x2 FMAs ----------------
constexpr int SMEM_FLOATS = 2 * 64 * 128 + 2 * 64 * 64 + 128;

__global__ void __launch_bounds__(256, 2)
main_kernel(const float* __restrict__ x,
            const unsigned int* __restrict__ mask,
            const float* __restrict__ c00,
            const float* __restrict__ c01,
            const float* __restrict__ c10,
            const float* __restrict__ c11,
            float* __restrict__ out) {
    extern __shared__ float sm[];
    float* sXd = sm;                         // [k=64][q=128] XOR-swizzled
    float* sXt = sXd + 64 * 128;             // [k=64][q=128] XOR-swizzled
    float* sC0 = sXt + 64 * 128;             // [k=64][u=64]
    float* sC1 = sC0 + 64 * 64;
    float* sFp = sC1 + 64 * 64;              // [64]
    float* sFd = sFp + 64;                   // [64]

    const int p = blockIdx.x;
    const int n = blockIdx.y;
    const int tid = threadIdx.x;

    // direct tile: x[n,p,q,h] -> sXd[h][swz(q)]
    const float4* xrow4 = (const float4*)(x + ((size_t)(n * PP + p)) * PP * HH);
    #pragma unroll
    for (int it = 0; it < 8; ++it) {
        const int idx4 = tid + it * 256;           // [q][h/4]
        const float4 v = xrow4[idx4];
        const int q  = idx4 >> 4;
        const int h0 = (idx4 & 15) << 2;
        const int qs = q ^ ((idx4 & 7) << 3);
        sXd[(h0 + 0) * 128 + qs] = v.x;
        sXd[(h0 + 1) * 128 + qs] = v.y;
        sXd[(h0 + 2) * 128 + qs] = v.z;
        sXd[(h0 + 3) * 128 + qs] = v.w;
    }
    // transposed tile: x[n,r,p,h] -> sXt[h][swz(r)]
    {
        const int h0 = (tid & 15) << 2;
        const int sw = (tid & 7) << 3;
        #pragma unroll
        for (int it = 0; it < 8; ++it) {
            const int r = (tid >> 4) + it * 16;
            const float4 v = *(const float4*)(x + (((size_t)(n * PP + r)) * PP + p) * HH + h0);
            const int rs = r ^ sw;
            sXt[(h0 + 0) * 128 + rs] = v.x;
            sXt[(h0 + 1) * 128 + rs] = v.y;
            sXt[(h0 + 2) * 128 + rs] = v.z;
            sXt[(h0 + 3) * 128 + rs] = v.w;
        }
    }
    // compute C0/C1 in-block from raw coefficients
    #pragma unroll
    for (int it = 0; it < 16; ++it) {
        const int idx = tid + it * 256;      // 0..4095 = h*64+u
        const int h = idx >> 6;
        const int uu = idx & 63;
        const float r = c10[idx] * c11[idx];
        sC0[idx] = c00[h * BB + 0] * c01[uu] * r;
        sC1[idx] = c00[h * BB + 1] * c01[UU + uu] * r;
    }
    if (tid < 64) {
        sFp[tid] = g_Fp[(n * PP + p) * UU + tid];
        sFd[tid] = g_Fd[(n * PP + p) * UU + tid];
    }
    __syncthreads();

    const int tx = tid & 15;
    const int ty = tid >> 4;
    const int u0 = tx << 2;
    const int q0 = ty << 3;

    unsigned long long acc[4][4];
    #pragma unroll
    for (int i = 0; i < 4; ++i)
        #pragma unroll
        for (int j = 0; j < 4; ++j) acc[i][j] = 0ULL;

    #pragma unroll 4
    for (int k = 0; k < 64; ++k) {
        const float4 b0 = *(const float4*)(sC0 + k * 64 + u0);
        const float4 b1 = *(const float4*)(sC1 + k * 64 + u0);
        unsigned long long bb0[4], bb1[4];
        PK2(bb0[0], b0.x); PK2(bb0[1], b0.y); PK2(bb0[2], b0.z); PK2(bb0[3], b0.w);
        PK2(bb1[0], b1.x); PK2(bb1[1], b1.y); PK2(bb1[2], b1.z); PK2(bb1[3], b1.w);
        const int kq = k * 128 + (q0 ^ (((k >> 2) & 7) << 3));
        const ulonglong2 a01 = *(const ulonglong2*)(sXd + kq);
        const ulonglong2 a23 = *(const ulonglong2*)(sXd + kq + 4);
        const ulonglong2 t01 = *(const ulonglong2*)(sXt + kq);
        const ulonglong2 t23 = *(const ulonglong2*)(sXt + kq + 4);
        const unsigned long long av[4] = {a01.x, a01.y, a23.x, a23.y};
        const unsigned long long tv[4] = {t01.x, t01.y, t23.x, t23.y};
        #pragma unroll
        for (int qp = 0; qp < 4; ++qp)
            #pragma unroll
            for (int j = 0; j < 4; ++j) {
                FMA2(acc[qp][j], av[qp], bb0[j]);
                FMA2(acc[qp][j], tv[qp], bb1[j]);
            }
    }

    // epilogue
    const float4 fp4 = *(const float4*)(sFp + u0);
    const float4 fd4 = *(const float4*)(sFd + u0);
    const unsigned int* em = mask + (size_t)(n * PP + p) * PP;
    #pragma unroll
    for (int qp = 0; qp < 4; ++qp) {
        float lo[4], hi[4];
        #pragma unroll
        for (int j = 0; j < 4; ++j) UPK2(lo[j], hi[j], acc[qp][j]);
        #pragma unroll
        for (int half = 0; half < 2; ++half) {
            const int q = q0 + 2 * qp + half;
            const float* v = half ? hi : lo;
            const float4 fq = *(const float4*)(g_Fq + ((size_t)(n * PP + q)) * UU + u0);
            const float msk = (em[q] != 0u) ? 1.0f : 0.0f;
            const float de = (q == p) ? 1.0f : 0.0f;
            float4 o;
            o.x = (v[0] + fq.x + fp4.x + de * fd4.x) * msk;
            o.y = (v[1] + fq.y + fp4.y + de * fd4.y) * msk;
            o.z = (v[2] + fq.z + fp4.z + de * fd4.z) * msk;
            o.w = (v[3] + fq.w + fp4.w + de * fd4.w) * msk;
            *(float4*)(out + (((size_t)(n * PP + p)) * PP + q) * UU + u0) = o;
        }
    }
}

// ---------------- launch ----------------
extern "C" void kernel_launch(void* const* d_in, const int* in_sizes, int n_in,
                              void* d_out, int out_size) {
    (void)in_sizes; (void)n_in; (void)out_size;
    const float*        x      = (const float*)d_in[0];
    const unsigned int* mask   = (const unsigned int*)d_in[1];
    const float*        npart  = (const float*)d_in[2];
    const float*        alpha0 = (const float*)d_in[3];
    const float*        c00    = (const float*)d_in[4];
    const float*        c01    = (const float*)d_in[5];
    const float*        c10    = (const float*)d_in[6];
    const float*        c11    = (const float*)d_in[7];
    const float*        bias   = (const float*)d_in[8];
    const float*        dbias  = (const float*)d_in[9];
    float* out = (float*)d_out;

    fuse_kernel<<<dim3(32, NN), 256>>>(x, npart);
    pro_kernel<<<dim3(32, NN), 256>>>(npart, alpha0, c00, c01, c10, c11, bias, dbias);

    cudaFuncSetAttribute(main_kernel, cudaFuncAttributeMaxDynamicSharedMemorySize,
                         SMEM_FLOATS * 4);
    main_kernel<<<dim3(PP, NN), 256, SMEM_FLOATS * 4>>>(x, mask, c00, c01, c10, c11, out);
}